// round 14
// baseline (speedup 1.0000x reference)
#include <cuda_runtime.h>

#define MAXN 100000
#define EPS_F 1e-8f
#define EPS_D 1e-8

// Scratch (allocation-free rule: __device__ globals)
__device__ float4 g_nodes[MAXN];          // pos.xyz, phi  (1.6 MB, L2-resident)
__device__ float  g_acc[MAXN * 12];       // per node: b0,b1,b2,a00 | a01,a02,a11,a12 | a22,pad,pad,pad

__device__ __forceinline__ void red_add_v4(float* addr, float a, float b, float c, float d) {
    asm volatile("red.global.add.v4.f32 [%0], {%1, %2, %3, %4};"
                 :: "l"(addr), "f"(a), "f"(b), "f"(c), "f"(d) : "memory");
}

__global__ void pack_zero_kernel(const float* __restrict__ pos,
                                 const float* __restrict__ phi, int n) {
    int i = blockIdx.x * blockDim.x + threadIdx.x;
    if (i >= n) return;
    g_nodes[i] = make_float4(pos[3 * i], pos[3 * i + 1], pos[3 * i + 2], phi[i]);
    float4 z = make_float4(0.f, 0.f, 0.f, 0.f);
    float4* a = reinterpret_cast<float4*>(g_acc + 12 * i);
    a[0] = z; a[1] = z; a[2] = z;
}

// Process only the first half of the symmetrized edge list; each undirected
// edge contributes IDENTICAL (A, b) increments to both endpoints:
//   outer(dx,dx) invariant under dx -> -dx;  (dphi*dx) invariant under joint negation.
__global__ void edge_kernel(const int* __restrict__ rows,
                            const int* __restrict__ cols, int ehalf) {
    int i = blockIdx.x * blockDim.x + threadIdx.x;
    if (i >= ehalf) return;
    int u = rows[i];
    int v = cols[i];
    float4 nu = g_nodes[u];
    float4 nv = g_nodes[v];
    float dx = nv.x - nu.x, dy = nv.y - nu.y, dz = nv.z - nu.z;
    float dphi = nv.w - nu.w;
    float d = sqrtf(dx * dx + dy * dy + dz * dz);
    float t = d + EPS_F;
    float w = 1.0f / (t * t);
    float wd = w * dphi;
    float b0 = wd * dx, b1 = wd * dy, b2 = wd * dz;
    float a00 = w * dx * dx, a01 = w * dx * dy, a02 = w * dx * dz;
    float a11 = w * dy * dy, a12 = w * dy * dz, a22 = w * dz * dz;

    float* pu = g_acc + 12 * u;
    red_add_v4(pu,     b0,  b1,  b2,  a00);
    red_add_v4(pu + 4, a01, a02, a11, a12);
    atomicAdd(pu + 8, a22);

    float* pv = g_acc + 12 * v;
    red_add_v4(pv,     b0,  b1,  b2,  a00);
    red_add_v4(pv + 4, a01, a02, a11, a12);
    atomicAdd(pv + 8, a22);
}

// (A + eps*I) x = b, A symmetric 3x3, solved via adjugate in double.
__global__ void solve_kernel(float* __restrict__ out, int n) {
    int i = blockIdx.x * blockDim.x + threadIdx.x;
    if (i >= n) return;
    const float4* ap = reinterpret_cast<const float4*>(g_acc + 12 * i);
    float4 q0 = ap[0];   // b0,b1,b2,a00
    float4 q1 = ap[1];   // a01,a02,a11,a12
    float  a22 = g_acc[12 * i + 8];

    double b0 = q0.x, b1 = q0.y, b2 = q0.z;
    double m00 = (double)q0.w + EPS_D;
    double m01 = q1.x, m02 = q1.y;
    double m11 = (double)q1.z + EPS_D;
    double m12 = q1.w;
    double m22 = (double)a22 + EPS_D;

    double c00 = m11 * m22 - m12 * m12;
    double c01 = m02 * m12 - m01 * m22;
    double c02 = m01 * m12 - m02 * m11;
    double c11 = m00 * m22 - m02 * m02;
    double c12 = m01 * m02 - m00 * m12;
    double c22 = m00 * m11 - m01 * m01;
    double det = m00 * c00 + m01 * c01 + m02 * c02;
    double inv = 1.0 / det;

    double x0 = (c00 * b0 + c01 * b1 + c02 * b2) * inv;
    double x1 = (c01 * b0 + c11 * b1 + c12 * b2) * inv;
    double x2 = (c02 * b0 + c12 * b1 + c22 * b2) * inv;

    out[3 * i]     = (float)x0;
    out[3 * i + 1] = (float)x1;
    out[3 * i + 2] = (float)x2;
}

extern "C" void kernel_launch(void* const* d_in, const int* in_sizes, int n_in,
                              void* d_out, int out_size) {
    const float* pos = (const float*)d_in[0];
    const float* phi = (const float*)d_in[1];
    const int*   ei  = (const int*)d_in[2];
    float* out = (float*)d_out;

    int  n      = in_sizes[1];            // N nodes (phi element count)
    long etotal = (long)in_sizes[2] / 2;  // undirected (symmetrized) edge count
    int  ehalf  = (int)(etotal / 2);      // unique edges before symmetrization

    const int TB = 256;
    pack_zero_kernel<<<(n + TB - 1) / TB, TB>>>(pos, phi, n);
    edge_kernel<<<(ehalf + TB - 1) / TB, TB>>>(ei, ei + etotal, ehalf);
    solve_kernel<<<(n + TB - 1) / TB, TB>>>(out, n);
}